// round 1
// baseline (speedup 1.0000x reference)
#include <cuda_runtime.h>

// Problem constants (fixed by the reference setup_inputs)
#define BB 8
#define CC 512
#define RR 128
#define HW (128 * 128)
#define NPLANE (BB * CC)          // 4096 planes of 16384 floats each

// Scratch (no allocations allowed in kernel_launch)
__device__ float g_sums[NPLANE];
__device__ float g_bias[NPLANE];

// ---------------------------------------------------------------------------
// Kernel 1: per-(b,c) plane sum. One 256-thread CTA per plane.
// 16384 floats = 4096 float4 = 16 float4 per thread, fully coalesced.
// ---------------------------------------------------------------------------
__global__ __launch_bounds__(256) void reduce_kernel(const float* __restrict__ x) {
    const int plane = blockIdx.x;
    const float4* __restrict__ p =
        reinterpret_cast<const float4*>(x + (size_t)plane * HW);
    const int tid = threadIdx.x;

    float s = 0.0f;
#pragma unroll
    for (int i = 0; i < HW / 4 / 256; ++i) {
        float4 v = p[tid + i * 256];
        s += (v.x + v.y) + (v.z + v.w);
    }

    // warp tree reduce
#pragma unroll
    for (int o = 16; o > 0; o >>= 1)
        s += __shfl_xor_sync(0xffffffffu, s, o);

    __shared__ float ws[8];
    if ((tid & 31) == 0) ws[tid >> 5] = s;
    __syncthreads();
    if (tid < 8) {
        float t = ws[tid];
#pragma unroll
        for (int o = 4; o > 0; o >>= 1)
            t += __shfl_xor_sync(0x000000ffu, t, o);
        if (tid == 0) g_sums[plane] = t;
    }
}

// ---------------------------------------------------------------------------
// Kernel 2: bias[b,c] from sums. One CTA per batch, 512 threads.
//   y  = sums / HW                       [512]
//   y1 = relu6(w_guide @ y)              [128]
//   bias = relu6(BN(w_fuse @ y1))        [512]
// ---------------------------------------------------------------------------
__global__ __launch_bounds__(512) void mid_kernel(
    const float* __restrict__ w_guide,   // [R, C] row-major
    const float* __restrict__ w_fuse,    // [C, R] row-major
    const float* __restrict__ bn_gamma,
    const float* __restrict__ bn_beta,
    const float* __restrict__ bn_mean,
    const float* __restrict__ bn_var) {
    const int b = blockIdx.x;
    const int t = threadIdx.x;

    __shared__ float y[CC];
    __shared__ float y1[RR];

    y[t] = g_sums[b * CC + t] * (1.0f / (float)HW);
    __syncthreads();

    if (t < RR) {
        const float* __restrict__ row = w_guide + t * CC;
        float acc = 0.0f;
#pragma unroll 8
        for (int c = 0; c < CC; ++c) acc = fmaf(row[c], y[c], acc);
        y1[t] = fminf(fmaxf(acc, 0.0f), 6.0f);
    }
    __syncthreads();

    const float* __restrict__ row = w_fuse + t * RR;
    float acc = 0.0f;
#pragma unroll 8
    for (int r = 0; r < RR; ++r) acc = fmaf(row[r], y1[r], acc);

    const float inv_std = rsqrtf(bn_var[t] + 1e-5f);
    float v = fmaf((acc - bn_mean[t]) * inv_std, bn_gamma[t], bn_beta[t]);
    g_bias[b * CC + t] = fminf(fmaxf(v, 0.0f), 6.0f);
}

// ---------------------------------------------------------------------------
// Kernel 3: out = x + bias[plane], streamed. One CTA per plane.
// ---------------------------------------------------------------------------
__global__ __launch_bounds__(256) void add_kernel(const float* __restrict__ x,
                                                  float* __restrict__ out) {
    const int plane = blockIdx.x;
    const float bias = g_bias[plane];
    const float4* __restrict__ p =
        reinterpret_cast<const float4*>(x + (size_t)plane * HW);
    float4* __restrict__ o =
        reinterpret_cast<float4*>(out + (size_t)plane * HW);
    const int tid = threadIdx.x;

#pragma unroll
    for (int i = 0; i < HW / 4 / 256; ++i) {
        float4 v = p[tid + i * 256];
        v.x += bias; v.y += bias; v.z += bias; v.w += bias;
        o[tid + i * 256] = v;
    }
}

extern "C" void kernel_launch(void* const* d_in, const int* in_sizes, int n_in,
                              void* d_out, int out_size) {
    const float* x        = (const float*)d_in[0];
    const float* w_guide  = (const float*)d_in[1];
    const float* w_fuse   = (const float*)d_in[2];
    const float* bn_gamma = (const float*)d_in[3];
    const float* bn_beta  = (const float*)d_in[4];
    const float* bn_mean  = (const float*)d_in[5];
    const float* bn_var   = (const float*)d_in[6];
    float* out = (float*)d_out;

    reduce_kernel<<<NPLANE, 256>>>(x);
    mid_kernel<<<BB, 512>>>(w_guide, w_fuse, bn_gamma, bn_beta, bn_mean, bn_var);
    add_kernel<<<NPLANE, 256>>>(x, out);
}

// round 2
// speedup vs baseline: 1.4021x; 1.4021x over previous
#include <cuda_runtime.h>

// Problem constants (fixed by the reference setup_inputs)
#define BB 8
#define CC 512
#define RR 128
#define HW (128 * 128)
#define NPLANE (BB * CC)          // 4096 planes of 16384 floats each

// Scratch (no allocations allowed in kernel_launch)
__device__ float g_sums[NPLANE];
__device__ float g_bias[NPLANE];

// ---------------------------------------------------------------------------
// Kernel 1: per-(b,c) plane sum. One 256-thread CTA per plane.
// 16384 floats = 4096 float4 = 16 float4 per thread, fully coalesced.
// ---------------------------------------------------------------------------
__global__ __launch_bounds__(256) void reduce_kernel(const float* __restrict__ x) {
    const int plane = blockIdx.x;
    const float4* __restrict__ p =
        reinterpret_cast<const float4*>(x + (size_t)plane * HW);
    const int tid = threadIdx.x;

    float s = 0.0f;
#pragma unroll
    for (int i = 0; i < HW / 4 / 256; ++i) {
        float4 v = p[tid + i * 256];
        s += (v.x + v.y) + (v.z + v.w);
    }

    // warp tree reduce
#pragma unroll
    for (int o = 16; o > 0; o >>= 1)
        s += __shfl_xor_sync(0xffffffffu, s, o);

    __shared__ float ws[8];
    if ((tid & 31) == 0) ws[tid >> 5] = s;
    __syncthreads();
    if (tid < 8) {
        float t = ws[tid];
#pragma unroll
        for (int o = 4; o > 0; o >>= 1)
            t += __shfl_xor_sync(0x000000ffu, t, o);
        if (tid == 0) g_sums[plane] = t;
    }
}

// ---------------------------------------------------------------------------
// Kernel 2: bias[b,c] from sums. One CTA per batch, 512 threads (16 warps).
// Warp-cooperative dot products: coalesced float4 row loads + shuffle reduce.
//   y  = sums / HW                       [512]
//   y1 = relu6(w_guide @ y)              [128]
//   bias = relu6(BN(w_fuse @ y1))        [512]
// ---------------------------------------------------------------------------
__global__ __launch_bounds__(512) void mid_kernel(
    const float* __restrict__ w_guide,   // [R, C] row-major
    const float* __restrict__ w_fuse,    // [C, R] row-major
    const float* __restrict__ bn_gamma,
    const float* __restrict__ bn_beta,
    const float* __restrict__ bn_mean,
    const float* __restrict__ bn_var) {
    const int b    = blockIdx.x;
    const int t    = threadIdx.x;
    const int wid  = t >> 5;             // 0..15
    const int lane = t & 31;

    __shared__ float y[CC];
    __shared__ float y1[RR];

    y[t] = g_sums[b * CC + t] * (1.0f / (float)HW);
    __syncthreads();

    // ---- y1[r] = relu6( dot(w_guide[r, :], y) ), one warp per output r ----
    // r = wid + 16*k, k in 0..7. Row is 512 floats = 128 float4; lane reads
    // float4 at [lane + 32*j], j in 0..3 — fully coalesced.
#pragma unroll
    for (int k = 0; k < RR / 16; ++k) {
        const int r = wid + 16 * k;
        const float4* __restrict__ row =
            reinterpret_cast<const float4*>(w_guide + (size_t)r * CC);
        float acc = 0.0f;
#pragma unroll
        for (int j = 0; j < 4; ++j) {
            float4 w = row[lane + 32 * j];
            const float* yy = &y[4 * (lane + 32 * j)];
            acc = fmaf(w.x, yy[0], acc);
            acc = fmaf(w.y, yy[1], acc);
            acc = fmaf(w.z, yy[2], acc);
            acc = fmaf(w.w, yy[3], acc);
        }
#pragma unroll
        for (int o = 16; o > 0; o >>= 1)
            acc += __shfl_xor_sync(0xffffffffu, acc, o);
        if (lane == 0) y1[r] = fminf(fmaxf(acc, 0.0f), 6.0f);
    }
    __syncthreads();

    // ---- bias[c] = relu6(BN(dot(w_fuse[c, :], y1))), one warp per output c --
    // c = wid + 16*k, k in 0..31. Row is 128 floats = 32 float4; lane reads
    // one float4 — fully coalesced 512B per warp.
#pragma unroll
    for (int k = 0; k < CC / 16; ++k) {
        const int c = wid + 16 * k;
        const float4* __restrict__ row =
            reinterpret_cast<const float4*>(w_fuse + (size_t)c * RR);
        float4 w = row[lane];
        const float* yy = &y1[4 * lane];
        float acc = w.x * yy[0];
        acc = fmaf(w.y, yy[1], acc);
        acc = fmaf(w.z, yy[2], acc);
        acc = fmaf(w.w, yy[3], acc);
#pragma unroll
        for (int o = 16; o > 0; o >>= 1)
            acc += __shfl_xor_sync(0xffffffffu, acc, o);
        if (lane == 0) {
            const float inv_std = rsqrtf(bn_var[c] + 1e-5f);
            float v = fmaf((acc - bn_mean[c]) * inv_std, bn_gamma[c], bn_beta[c]);
            g_bias[b * CC + c] = fminf(fmaxf(v, 0.0f), 6.0f);
        }
    }
}

// ---------------------------------------------------------------------------
// Kernel 3: out = x + bias[plane], streamed. One CTA per plane.
// Planes processed in REVERSE order: the tail of x that the reduce pass left
// resident in L2 (~126MB) is read first, converting DRAM reads to L2 hits.
// Output stores use evict-first (.cs) to avoid displacing that resident tail.
// ---------------------------------------------------------------------------
__global__ __launch_bounds__(256) void add_kernel(const float* __restrict__ x,
                                                  float* __restrict__ out) {
    const int plane = NPLANE - 1 - blockIdx.x;
    const float bias = g_bias[plane];
    const float4* __restrict__ p =
        reinterpret_cast<const float4*>(x + (size_t)plane * HW);
    float4* __restrict__ o =
        reinterpret_cast<float4*>(out + (size_t)plane * HW);
    const int tid = threadIdx.x;

#pragma unroll
    for (int i = 0; i < HW / 4 / 256; ++i) {
        float4 v = p[tid + i * 256];
        v.x += bias; v.y += bias; v.z += bias; v.w += bias;
        __stcs(&o[tid + i * 256], v);
    }
}

extern "C" void kernel_launch(void* const* d_in, const int* in_sizes, int n_in,
                              void* d_out, int out_size) {
    const float* x        = (const float*)d_in[0];
    const float* w_guide  = (const float*)d_in[1];
    const float* w_fuse   = (const float*)d_in[2];
    const float* bn_gamma = (const float*)d_in[3];
    const float* bn_beta  = (const float*)d_in[4];
    const float* bn_mean  = (const float*)d_in[5];
    const float* bn_var   = (const float*)d_in[6];
    float* out = (float*)d_out;

    reduce_kernel<<<NPLANE, 256>>>(x);
    mid_kernel<<<BB, 512>>>(w_guide, w_fuse, bn_gamma, bn_beta, bn_mean, bn_var);
    add_kernel<<<NPLANE, 256>>>(x, out);
}